// round 1
// baseline (speedup 1.0000x reference)
#include <cuda_runtime.h>
#include <math.h>

// Problem constants (fixed by the dataset)
#define VOCAB   32000
#define NBL     128        // B*L = 2*64
#define NK      64         // H (8 heads x 8 hph)
#define HEADS   8

// Tiling for the main kernel
#define BM      32         // bl tile
#define BN      128        // vocab tile
#define TM      4
#define TN      4
#define NTHREADS 256       // (BM/TM)*(BN/TN) = 8*32

// Device scratch (static globals — no runtime allocation).
// Transposed layouts [k][...] for coalesced tile loads in the main kernel.
__device__ float4 g_bl[NK * NBL];        // [k][bl] = {cp, e^f, e^-f, 0}
__device__ float2 g_vexp[NK * VOCAB];    // [k][v]  = {e^-vp, e^vp}

// ---------------------------------------------------------------------------
// Precompute per-(bl,k): cp = W[h]*amps*cos(phases - iph[k]), e^{+-freqs}
// ---------------------------------------------------------------------------
__global__ void prep_bl_kernel(const float* __restrict__ freqs,
                               const float* __restrict__ amps,
                               const float* __restrict__ phases,
                               const float* __restrict__ iph,
                               const float* __restrict__ W) {
    int i = blockIdx.x * blockDim.x + threadIdx.x;   // i = bl*NK + k
    if (i >= NBL * NK) return;
    int k  = i & (NK - 1);
    int bl = i >> 6;
    float c  = amps[i] * cosf(phases[i] - iph[k]);
    float cp = c * W[k >> 3];
    float f  = freqs[i];
    g_bl[k * NBL + bl] = make_float4(cp, expf(f), expf(-f), 0.0f);
}

// ---------------------------------------------------------------------------
// Precompute per-(v,k): e^{+-vocab_patterns}, stored transposed [k][v]
// ---------------------------------------------------------------------------
__global__ void prep_v_kernel(const float* __restrict__ vp) {
    long i = (long)blockIdx.x * blockDim.x + threadIdx.x;   // i = k*VOCAB + v (output order)
    if (i >= (long)NK * VOCAB) return;
    int k = (int)(i / VOCAB);
    int v = (int)(i - (long)k * VOCAB);
    float x = vp[(long)v * NK + k];     // input layout [v][h][j] = [v][k]
    g_vexp[i] = make_float2(expf(-x), expf(x));
}

// ---------------------------------------------------------------------------
// Main kernel: out[bl][v] = sum_k cp * min(e^f * e^-vp, e^-f * e^vp) + bias
// GEMM-like tiling, full K resident in shared memory, one __syncthreads().
// ---------------------------------------------------------------------------
__global__ void __launch_bounds__(NTHREADS, 2)
main_kernel(float* __restrict__ out, const float* __restrict__ bptr) {
    extern __shared__ char smem_raw[];
    float2* s_v  = (float2*)smem_raw;                                   // [NK][BN]
    float4* s_bl = (float4*)(smem_raw + (size_t)NK * BN * sizeof(float2)); // [NK][BM]

    const int tid     = threadIdx.x;
    const int v_base  = blockIdx.x * BN;
    const int bl_base = blockIdx.y * BM;

    // Load vocab tile: g_vexp[k][v_base+v] -> s_v[k][v]   (coalesced LDG + STS)
    #pragma unroll
    for (int it = 0; it < (BN * NK) / NTHREADS; ++it) {
        int idx = tid + it * NTHREADS;
        int v   = idx & (BN - 1);
        int k   = idx >> 7;                       // idx / BN
        s_v[k * BN + v] = g_vexp[(long)k * VOCAB + v_base + v];
    }
    // Load bl tile: g_bl[k][bl_base+bl] -> s_bl[k][bl]    (coalesced LDG.128)
    #pragma unroll
    for (int it = 0; it < (BM * NK) / NTHREADS; ++it) {
        int idx = tid + it * NTHREADS;
        int bl  = idx & (BM - 1);
        int k   = idx >> 5;                       // idx / BM
        s_bl[k * BM + bl] = g_bl[k * NBL + bl_base + bl];
    }
    __syncthreads();

    const int vcol  = tid & 31;
    const int blrow = tid >> 5;                   // warp-uniform -> smem broadcast
    const int v0    = vcol * TN;
    const int bl0   = blrow * TM;

    float acc[TM][TN];
    #pragma unroll
    for (int i = 0; i < TM; ++i)
        #pragma unroll
        for (int j = 0; j < TN; ++j) acc[i][j] = 0.0f;

    #pragma unroll 8
    for (int k = 0; k < NK; ++k) {
        float4 blv[TM];
        const float4* sb = &s_bl[k * BM + bl0];
        #pragma unroll
        for (int i = 0; i < TM; ++i) blv[i] = sb[i];

        // 4 consecutive float2 vocab pairs as 2x LDS.128
        const float4* sv = (const float4*)(&s_v[k * BN + v0]);
        float4 va = sv[0];   // {em0, ep0, em1, ep1}
        float4 vb = sv[1];   // {em2, ep2, em3, ep3}

        #pragma unroll
        for (int i = 0; i < TM; ++i) {
            float cp = blv[i].x, ep = blv[i].y, em = blv[i].z;
            acc[i][0] = fmaf(cp, fminf(ep * va.x, em * va.y), acc[i][0]);
            acc[i][1] = fmaf(cp, fminf(ep * va.z, em * va.w), acc[i][1]);
            acc[i][2] = fmaf(cp, fminf(ep * vb.x, em * vb.y), acc[i][2]);
            acc[i][3] = fmaf(cp, fminf(ep * vb.z, em * vb.w), acc[i][3]);
        }
    }

    const float bias = bptr[0];
    #pragma unroll
    for (int i = 0; i < TM; ++i) {
        float4 r = make_float4(acc[i][0] + bias, acc[i][1] + bias,
                               acc[i][2] + bias, acc[i][3] + bias);
        *(float4*)&out[(size_t)(bl_base + bl0 + i) * VOCAB + v_base + v0] = r;
    }
}

// ---------------------------------------------------------------------------
extern "C" void kernel_launch(void* const* d_in, const int* in_sizes, int n_in,
                              void* d_out, int out_size) {
    const float* freqs  = (const float*)d_in[0];
    const float* amps   = (const float*)d_in[1];
    const float* phases = (const float*)d_in[2];
    const float* vp     = (const float*)d_in[3];
    const float* iph    = (const float*)d_in[4];
    const float* W      = (const float*)d_in[5];
    const float* b      = (const float*)d_in[6];
    float* out = (float*)d_out;

    // Precompute tables
    prep_bl_kernel<<<(NBL * NK + 255) / 256, 256>>>(freqs, amps, phases, iph, W);
    prep_v_kernel<<<((long)NK * VOCAB + 255) / 256, 256>>>(vp);

    // Main pass
    const int smem_bytes = NK * BN * (int)sizeof(float2) + NK * BM * (int)sizeof(float4); // 98304
    static bool attr_set = false;
    // cudaFuncSetAttribute is idempotent and capture-safe (no stream op); call every time
    cudaFuncSetAttribute(main_kernel, cudaFuncAttributeMaxDynamicSharedMemorySize, smem_bytes);
    (void)attr_set;

    dim3 grid(VOCAB / BN, NBL / BM);   // (250, 4)
    main_kernel<<<grid, NTHREADS, smem_bytes>>>(out, b);
    (void)in_sizes; (void)n_in; (void)out_size;
}